// round 10
// baseline (speedup 1.0000x reference)
#include <cuda_runtime.h>
#include <stdint.h>

// Problem shapes (fixed by the dataset).
#define BB 64
#define PP 2048
#define GG 512
#define NZ 16
#define GH (GG / NZ)    // 32 gts per tile

// Merged best per (image, pred): (iou_bits<<32) | (511 - g). Zero-initialized;
// only written by the rare slow path; K2a resets after consuming (replay-safe).
__device__ unsigned long long g_best[BB * PP];
// Dense per (image, pred): (rank<<9) | ginv. 0xFFFFFFFF = not a candidate.
__device__ unsigned int g_cand[BB * PP];
__device__ float g_ap[BB];
__device__ unsigned int g_ticket;   // zero-init; self-resetting via atomicInc wrap

// ---------------------------------------------------------------------------
// K1: per (image, pred, gt-tile): cheap exact-f32 screen for "any gt in tile
// with IoU > 0.5"; only screened-in (pred,tile) pairs run the exact argmax
// and merge via u64 atomicMax. Argmax identity below 0.5 never affects the
// reference output (tp requires iou > 0.5), so the fast path writes nothing.
// Screen: iou > 0.5  <=>  3*inter > pa+ga; tested as inter > 0.333*(pa+ga)
// (0.333f < 1/3 gives a 1e-3 RELATIVE margin -> no false negatives, scale-free).
// 256 threads, 2 preds/thread, 32 gts in smem. grid = (PP/512, BB, NZ).
// ---------------------------------------------------------------------------
__global__ __launch_bounds__(256) void k_bestiou(
    const float* __restrict__ pred_boxes,   // [B,P,4] xywh
    const float* __restrict__ gt_boxes)     // [B,G,4] xywh
{
    const int b  = blockIdx.y;
    const int zt = blockIdx.z;
    const int p0 = blockIdx.x * 512 + threadIdx.x;
    const int p1 = p0 + 256;

    __shared__ float4 sbox[GH];   // x1,y1,x2,y2
    __shared__ float2 ssa[GH];    // {exact area, area*0.333f}

    const float4* gbp = reinterpret_cast<const float4*>(
        gt_boxes + ((size_t)b * GG + (size_t)zt * GH) * 4);
    if (threadIdx.x < GH) {
        float4 v = gbp[threadIdx.x];
        float x2 = v.x + v.z;
        float y2 = v.y + v.w;
        float ar = fabsf((x2 - v.x) * (y2 - v.y));
        sbox[threadIdx.x] = make_float4(v.x, v.y, x2, y2);
        ssa[threadIdx.x]  = make_float2(ar, ar * 0.333f);
    }
    __syncthreads();

    const float4* pbp = reinterpret_cast<const float4*>(pred_boxes + (size_t)b * PP * 4);
    float4 q0 = pbp[p0];
    float4 q1 = pbp[p1];
    const float ax1 = q0.x, ay1 = q0.y, ax2 = q0.x + q0.z, ay2 = q0.y + q0.w;
    const float bx1 = q1.x, by1 = q1.y, bx2 = q1.x + q1.z, by2 = q1.y + q1.w;
    const float apa = fabsf((ax2 - ax1) * (ay2 - ay1));
    const float bpa = fabsf((bx2 - bx1) * (by2 - by1));
    const float apa3 = apa * 0.333f;
    const float bpa3 = bpa * 0.333f;

    // Fast screen: tmin < 0  <=>  exists g with inter > 0.333*(pa+ga).
    // iw left unclamped (ih clamp makes n<=0 when either axis misses).
    float tmin0 = 0.0f, tmin1 = 0.0f;

#pragma unroll 8
    for (int g = 0; g < GH; ++g) {
        float4 gb  = sbox[g];
        float  sa3 = ssa[g].y;
        {
            float iw = fminf(ax2, gb.z) - fmaxf(ax1, gb.x);
            float ih = fmaxf(fminf(ay2, gb.w) - fmaxf(ay1, gb.y), 0.0f);
            float t  = fmaf(-iw, ih, apa3 + sa3);
            tmin0 = fminf(tmin0, t);
        }
        {
            float iw = fminf(bx2, gb.z) - fmaxf(bx1, gb.x);
            float ih = fmaxf(fminf(by2, gb.w) - fmaxf(by1, gb.y), 0.0f);
            float t  = fmaf(-iw, ih, bpa3 + sa3);
            tmin1 = fminf(tmin1, t);
        }
    }

    // Rare exact path: reference-formula IoU (both clamps, +eps, IEEE div),
    // first-max strict > over ascending g; u64 pack merges exactly across
    // tiles (iou desc, tie -> lower g).
    const int goff = zt * GH;
    if (tmin0 < 0.0f) {
        float best = 0.0f; int bg = 0;
        for (int g = 0; g < GH; ++g) {
            float4 gb = sbox[g];
            float  sa = ssa[g].x;
            float iw = fmaxf(fminf(ax2, gb.z) - fmaxf(ax1, gb.x), 0.0f);
            float ih = fmaxf(fminf(ay2, gb.w) - fmaxf(ay1, gb.y), 0.0f);
            float inter = iw * ih;
            float u   = apa + sa - inter + 1e-9f;
            float iou = inter / u;
            if (iou > best) { best = iou; bg = g; }
        }
        unsigned long long pack = ((unsigned long long)__float_as_uint(best) << 32)
                                | (unsigned)(511 - (bg + goff));
        atomicMax(&g_best[(size_t)b * PP + p0], pack);
    }
    if (tmin1 < 0.0f) {
        float best = 0.0f; int bg = 0;
        for (int g = 0; g < GH; ++g) {
            float4 gb = sbox[g];
            float  sa = ssa[g].x;
            float iw = fmaxf(fminf(bx2, gb.z) - fmaxf(bx1, gb.x), 0.0f);
            float ih = fmaxf(fminf(by2, gb.w) - fmaxf(by1, gb.y), 0.0f);
            float inter = iw * ih;
            float u   = bpa + sa - inter + 1e-9f;
            float iou = inter / u;
            if (iou > best) { best = iou; bg = g; }
        }
        unsigned long long pack = ((unsigned long long)__float_as_uint(best) << 32)
                                | (unsigned)(511 - (bg + goff));
        atomicMax(&g_best[(size_t)b * PP + p1], pack);
    }
}

// ---------------------------------------------------------------------------
// K2a: consume merged best (and reset it for the next graph replay), detect
// candidates, compute exact stable-sort rank for candidates only
// (warp-cooperative count). grid = (PP/256, BB), 256 threads.
// ---------------------------------------------------------------------------
__global__ __launch_bounds__(256) void k_cand(
    const float* __restrict__ pred_scores,   // [B,P]
    const int*   __restrict__ pred_classes,  // [B,P]
    const int*   __restrict__ gt_classes)    // [B,G]
{
    const int b   = blockIdx.y;
    const int tid = threadIdx.x;
    const int p   = blockIdx.x * 256 + tid;

    __shared__ float ssc[PP];   // all scores of image b

    const float4* sp = reinterpret_cast<const float4*>(pred_scores + (size_t)b * PP);
    for (int i = tid; i < PP / 4; i += 256)
        reinterpret_cast<float4*>(ssc)[i] = sp[i];
    __syncthreads();

    const size_t idx = (size_t)b * PP + p;
    unsigned long long v = g_best[idx];
    g_best[idx] = 0ULL;   // reset for next replay (this thread is sole reader)

    const int   ginv = (int)(v & 0x1FF);        // 511 - g
    const int   g    = 511 - ginv;
    const float biou = __uint_as_float((unsigned int)(v >> 32));
    const bool  cand = (biou > 0.5f) &&
                       (pred_classes[idx] == gt_classes[(size_t)b * GG + g]);

    const float ms   = ssc[p];
    const int   lane = tid & 31;
    const unsigned full = 0xFFFFFFFFu;

    unsigned int res = 0xFFFFFFFFu;
    unsigned bal = __ballot_sync(full, cand);
    while (bal) {
        int src = __ffs(bal) - 1;
        bal &= bal - 1;
        int   pc = __shfl_sync(full, p,  src);
        float sc = __shfl_sync(full, ms, src);
        int cnt = 0;
        // rank = #(q: score_q > score_p  ||  (score_q == score_p && q < p))
        for (int q = lane; q < PP; q += 32) {
            float sq = ssc[q];
            cnt += (sq > sc) || (sq == sc && q < pc);
        }
        cnt = __reduce_add_sync(full, cnt);
        if (lane == src) res = ((unsigned int)cnt << 9) | (unsigned int)ginv;
    }

    g_cand[idx] = cand ? res : 0xFFFFFFFFu;
}

// ---------------------------------------------------------------------------
// K2b: per image — compact candidates, greedy TP (min rank per gt), AP.
// Last block (ticket) computes the batch mean. grid = BB, 256 threads.
// ---------------------------------------------------------------------------
__global__ __launch_bounds__(256) void k_ap2(float* __restrict__ out)
{
    const int b   = blockIdx.x;
    const int tid = threadIdx.x;
    const int lane = tid & 31, wid = tid >> 5;

    __shared__ unsigned int  scomp[PP];
    __shared__ unsigned char stp[PP];
    __shared__ int   wsum[8];
    __shared__ float wred[8];

    // Load 8 entries each, count valid, block-scan for p-ordered compaction.
    unsigned int vals[8];
    int c = 0;
    const int base = tid * 8;
#pragma unroll
    for (int k = 0; k < 8; ++k) {
        vals[k] = g_cand[(size_t)b * PP + base + k];
        c += (vals[k] != 0xFFFFFFFFu) ? 1 : 0;
    }
    int sc = c;
    for (int o = 1; o < 32; o <<= 1) {
        int u = __shfl_up_sync(0xFFFFFFFFu, sc, o);
        if (lane >= o) sc += u;
    }
    if (lane == 31) wsum[wid] = sc;
    __syncthreads();
    if (wid == 0 && lane < 8) {
        int u = wsum[lane];
        for (int o = 1; o < 8; o <<= 1) {
            int w = __shfl_up_sync(0xFFu, u, o);
            if (lane >= o) u += w;
        }
        wsum[lane] = u;
    }
    __syncthreads();
    int off = (sc - c) + (wid > 0 ? wsum[wid - 1] : 0);
    const int n = wsum[7];
#pragma unroll
    for (int k = 0; k < 8; ++k)
        if (vals[k] != 0xFFFFFFFFu) scomp[off++] = vals[k];
    __syncthreads();

    // TP iff no other candidate with same gt and smaller rank.
    // packed = (rank<<9)|ginv: same ginv -> same gt; smaller packed -> smaller rank.
    for (int i = tid; i < n; i += 256) {
        unsigned int v = scomp[i];
        int tp = 1;
        for (int j = 0; j < n; ++j) {
            unsigned int w = scomp[j];
            if (w < v && !((w ^ v) & 0x1FFu)) tp = 0;
        }
        stp[i] = (unsigned char)tp;
    }
    __syncthreads();

    // AP terms. For a tp at global rank r (k = r+1), j = 1 + #(tps with rank < r):
    //   term = 0.5 * ( j/k + (k==1 ? 1 : (j-1)/(k-1)) );  AP = sum(term)/G.
    float acc = 0.0f;
    for (int i = tid; i < n; i += 256) {
        if (!stp[i]) continue;
        unsigned int v = scomp[i];
        unsigned int r = v >> 9;
        int j = 1;
        for (int m = 0; m < n; ++m)
            j += (stp[m] && (scomp[m] >> 9) < r) ? 1 : 0;
        float kk = (float)(r + 1);
        float pj = (float)j;
        float prev = (r == 0) ? 1.0f : (pj - 1.0f) / (kk - 1.0f);
        acc += 0.5f * (pj / kk + prev);
    }

    // Deterministic block reduce.
    for (int o = 16; o > 0; o >>= 1) acc += __shfl_down_sync(0xFFFFFFFFu, acc, o);
    if (lane == 0) wred[wid] = acc;
    __syncthreads();
    if (tid == 0) {
        float u = 0.0f;
#pragma unroll
        for (int w = 0; w < 8; ++w) u += wred[w];
        g_ap[b] = u / (float)GG;

        // Ticket: last block computes the mean. atomicInc wraps 63 -> 0, so the
        // counter self-resets for every graph replay.
        __threadfence();
        unsigned old = atomicInc(&g_ticket, BB - 1);
        if (old == BB - 1) {
            float s = 0.0f;
#pragma unroll
            for (int i = 0; i < BB; ++i) s += g_ap[i];   // fixed order
            out[0] = s * (1.0f / (float)BB);
        }
    }
}

// ---------------------------------------------------------------------------
extern "C" void kernel_launch(void* const* d_in, const int* in_sizes, int n_in,
                              void* d_out, int out_size)
{
    const float* pred_boxes   = (const float*)d_in[0];
    const float* pred_scores  = (const float*)d_in[1];
    const int*   pred_classes = (const int*)d_in[2];
    const float* gt_boxes     = (const float*)d_in[3];
    const int*   gt_classes   = (const int*)d_in[4];
    float* out = (float*)d_out;

    dim3 g1(PP / 512, BB, NZ);
    k_bestiou<<<g1, 256>>>(pred_boxes, gt_boxes);
    dim3 g2(PP / 256, BB);
    k_cand<<<g2, 256>>>(pred_scores, pred_classes, gt_classes);
    k_ap2<<<BB, 256>>>(out);
}

// round 12
// speedup vs baseline: 2.5552x; 2.5552x over previous
#include <cuda_runtime.h>
#include <stdint.h>

// Problem shapes (fixed by the dataset).
#define BB 64
#define PP 2048
#define GG 512
#define NZ 16
#define GH (GG / NZ)    // 32 gts per tile

// Merged best per (image, pred): (iou_bits<<32) | (511 - g). Zero-initialized;
// K2a resets each element after consuming it (replay-safe).
__device__ unsigned long long g_best[BB * PP];
// Dense per (image, pred): (rank<<9) | ginv. 0xFFFFFFFF = not a candidate.
__device__ unsigned int g_cand[BB * PP];
__device__ float g_ap[BB];
__device__ unsigned int g_ticket;   // zero-init; self-resetting via atomicInc wrap

// ---------------------------------------------------------------------------
// K1: per (image, pred, gt-tile) first-max argmax_g IoU + max value.
// In-loop argmax state is a single signed int key: (iou_bits & ~31) | (31-g).
//  - iou >= 0 keys: monotone in iou (5 low mantissa bits truncated, 2^-19 rel);
//    equal truncated iou -> larger (31-g) wins = lower g = reference first-max.
//  - negative iou (unclamped iw): sign bit set -> negative signed int -> loses.
//  - init key = 31 = pack(iou=0, g=0): all-nonpositive tiles resolve to g=0.
// Tile winner's IoU is recomputed exactly (reference formula) in the epilogue
// and merged across tiles via u64 atomicMax (iou desc, tie -> lower g).
// 256 threads, 2 preds/thread, 32 gts in smem. grid = (PP/512, BB, NZ).
// ---------------------------------------------------------------------------
__global__ __launch_bounds__(256) void k_bestiou(
    const float* __restrict__ pred_boxes,   // [B,P,4] xywh
    const float* __restrict__ gt_boxes)     // [B,G,4] xywh
{
    const int b  = blockIdx.y;
    const int zt = blockIdx.z;
    const int p0 = blockIdx.x * 512 + threadIdx.x;
    const int p1 = p0 + 256;

    __shared__ float4 sbox[GH];   // x1,y1,x2,y2
    __shared__ float  sarea[GH];  // exact area

    const float4* gbp = reinterpret_cast<const float4*>(
        gt_boxes + ((size_t)b * GG + (size_t)zt * GH) * 4);
    if (threadIdx.x < GH) {
        float4 v = gbp[threadIdx.x];
        float x2 = v.x + v.z;
        float y2 = v.y + v.w;
        sbox[threadIdx.x]  = make_float4(v.x, v.y, x2, y2);
        sarea[threadIdx.x] = fabsf((x2 - v.x) * (y2 - v.y));
    }
    __syncthreads();

    const float4* pbp = reinterpret_cast<const float4*>(pred_boxes + (size_t)b * PP * 4);
    float4 q0 = pbp[p0];
    float4 q1 = pbp[p1];
    const float ax1 = q0.x, ay1 = q0.y, ax2 = q0.x + q0.z, ay2 = q0.y + q0.w;
    const float bx1 = q1.x, by1 = q1.y, bx2 = q1.x + q1.z, by2 = q1.y + q1.w;
    const float apa = fabsf((ax2 - ax1) * (ay2 - ay1)) + 1e-9f;  // area + eps hoisted
    const float bpa = fabsf((bx2 - bx1) * (by2 - by1)) + 1e-9f;

    int key0 = 31;   // pack(iou = 0, g = 0)
    int key1 = 31;

#pragma unroll
    for (int g = 0; g < GH; ++g) {
        float4 gb = sbox[g];
        float  sa = sarea[g];
        {
            float iw = fminf(ax2, gb.z) - fmaxf(ax1, gb.x);   // unclamped
            float ih = fmaxf(fminf(ay2, gb.w) - fmaxf(ay1, gb.y), 0.0f);
            float n  = iw * ih;
            float u  = (apa + sa) - n;                        // >= eps, NaN-free
            float iou = __fdividef(n, u);
            int k = (__float_as_int(iou) & (int)0xFFFFFFE0) | (31 - g);
            key0 = max(key0, k);                              // signed IMNMX
        }
        {
            float iw = fminf(bx2, gb.z) - fmaxf(bx1, gb.x);
            float ih = fmaxf(fminf(by2, gb.w) - fmaxf(by1, gb.y), 0.0f);
            float n  = iw * ih;
            float u  = (bpa + sa) - n;
            float iou = __fdividef(n, u);
            int k = (__float_as_int(iou) & (int)0xFFFFFFE0) | (31 - g);
            key1 = max(key1, k);
        }
    }

    // Epilogue: exact f32 IoU (reference formula) for each pred's tile winner.
    const int goff = zt * GH;
    {
        int bg = 31 - (key0 & 31);
        float4 gf = sbox[bg];
        float  sa = sarea[bg];
        float iw = fmaxf(fminf(ax2, gf.z) - fmaxf(ax1, gf.x), 0.0f);
        float ih = fmaxf(fminf(ay2, gf.w) - fmaxf(ay1, gf.y), 0.0f);
        float n  = iw * ih;
        float u  = (apa + sa) - n;          // apa already has +1e-9
        float iou = n / u;                  // IEEE, >= 0
        unsigned long long pack = ((unsigned long long)__float_as_uint(iou) << 32)
                                | (unsigned)(511 - (bg + goff));
        atomicMax(&g_best[(size_t)b * PP + p0], pack);
    }
    {
        int bg = 31 - (key1 & 31);
        float4 gf = sbox[bg];
        float  sa = sarea[bg];
        float iw = fmaxf(fminf(bx2, gf.z) - fmaxf(bx1, gf.x), 0.0f);
        float ih = fmaxf(fminf(by2, gf.w) - fmaxf(by1, gf.y), 0.0f);
        float n  = iw * ih;
        float u  = (bpa + sa) - n;
        float iou = n / u;
        unsigned long long pack = ((unsigned long long)__float_as_uint(iou) << 32)
                                | (unsigned)(511 - (bg + goff));
        atomicMax(&g_best[(size_t)b * PP + p1], pack);
    }
}

// ---------------------------------------------------------------------------
// K2a: consume merged best (and reset it for the next graph replay), detect
// candidates, compute exact stable-sort rank for candidates only
// (warp-cooperative count). grid = (PP/256, BB), 256 threads.
// ---------------------------------------------------------------------------
__global__ __launch_bounds__(256) void k_cand(
    const float* __restrict__ pred_scores,   // [B,P]
    const int*   __restrict__ pred_classes,  // [B,P]
    const int*   __restrict__ gt_classes)    // [B,G]
{
    const int b   = blockIdx.y;
    const int tid = threadIdx.x;
    const int p   = blockIdx.x * 256 + tid;

    __shared__ float ssc[PP];   // all scores of image b

    const float4* sp = reinterpret_cast<const float4*>(pred_scores + (size_t)b * PP);
    for (int i = tid; i < PP / 4; i += 256)
        reinterpret_cast<float4*>(ssc)[i] = sp[i];
    __syncthreads();

    const size_t idx = (size_t)b * PP + p;
    unsigned long long v = g_best[idx];
    g_best[idx] = 0ULL;   // reset for next replay (this thread is sole reader)

    const int   ginv = (int)(v & 0x1FF);        // 511 - g
    const int   g    = 511 - ginv;
    const float biou = __uint_as_float((unsigned int)(v >> 32));
    const bool  cand = (biou > 0.5f) &&
                       (pred_classes[idx] == gt_classes[(size_t)b * GG + g]);

    const float ms   = ssc[p];
    const int   lane = tid & 31;
    const unsigned full = 0xFFFFFFFFu;

    unsigned int res = 0xFFFFFFFFu;
    unsigned bal = __ballot_sync(full, cand);
    while (bal) {
        int src = __ffs(bal) - 1;
        bal &= bal - 1;
        int   pc = __shfl_sync(full, p,  src);
        float sc = __shfl_sync(full, ms, src);
        int cnt = 0;
        // rank = #(q: score_q > score_p  ||  (score_q == score_p && q < p))
        for (int q = lane; q < PP; q += 32) {
            float sq = ssc[q];
            cnt += (sq > sc) || (sq == sc && q < pc);
        }
        cnt = __reduce_add_sync(full, cnt);
        if (lane == src) res = ((unsigned int)cnt << 9) | (unsigned int)ginv;
    }

    g_cand[idx] = cand ? res : 0xFFFFFFFFu;
}

// ---------------------------------------------------------------------------
// K2b: per image — compact candidates, greedy TP (min rank per gt), AP.
// Last block (ticket) computes the batch mean. grid = BB, 256 threads.
// ---------------------------------------------------------------------------
__global__ __launch_bounds__(256) void k_ap2(float* __restrict__ out)
{
    const int b   = blockIdx.x;
    const int tid = threadIdx.x;
    const int lane = tid & 31, wid = tid >> 5;

    __shared__ unsigned int  scomp[PP];
    __shared__ unsigned char stp[PP];
    __shared__ int   wsum[8];
    __shared__ float wred[8];

    // Load 8 entries each, count valid, block-scan for p-ordered compaction.
    unsigned int vals[8];
    int c = 0;
    const int base = tid * 8;
#pragma unroll
    for (int k = 0; k < 8; ++k) {
        vals[k] = g_cand[(size_t)b * PP + base + k];
        c += (vals[k] != 0xFFFFFFFFu) ? 1 : 0;
    }
    int sc = c;
    for (int o = 1; o < 32; o <<= 1) {
        int u = __shfl_up_sync(0xFFFFFFFFu, sc, o);
        if (lane >= o) sc += u;
    }
    if (lane == 31) wsum[wid] = sc;
    __syncthreads();
    if (wid == 0 && lane < 8) {
        int u = wsum[lane];
        for (int o = 1; o < 8; o <<= 1) {
            int w = __shfl_up_sync(0xFFu, u, o);
            if (lane >= o) u += w;
        }
        wsum[lane] = u;
    }
    __syncthreads();
    int off = (sc - c) + (wid > 0 ? wsum[wid - 1] : 0);
    const int n = wsum[7];
#pragma unroll
    for (int k = 0; k < 8; ++k)
        if (vals[k] != 0xFFFFFFFFu) scomp[off++] = vals[k];
    __syncthreads();

    // TP iff no other candidate with same gt and smaller rank.
    // packed = (rank<<9)|ginv: same ginv -> same gt; smaller packed -> smaller rank.
    for (int i = tid; i < n; i += 256) {
        unsigned int v = scomp[i];
        int tp = 1;
        for (int j = 0; j < n; ++j) {
            unsigned int w = scomp[j];
            if (w < v && !((w ^ v) & 0x1FFu)) tp = 0;
        }
        stp[i] = (unsigned char)tp;
    }
    __syncthreads();

    // AP terms. For a tp at global rank r (k = r+1), j = 1 + #(tps with rank < r):
    //   term = 0.5 * ( j/k + (k==1 ? 1 : (j-1)/(k-1)) );  AP = sum(term)/G.
    float acc = 0.0f;
    for (int i = tid; i < n; i += 256) {
        if (!stp[i]) continue;
        unsigned int v = scomp[i];
        unsigned int r = v >> 9;
        int j = 1;
        for (int m = 0; m < n; ++m)
            j += (stp[m] && (scomp[m] >> 9) < r) ? 1 : 0;
        float kk = (float)(r + 1);
        float pj = (float)j;
        float prev = (r == 0) ? 1.0f : (pj - 1.0f) / (kk - 1.0f);
        acc += 0.5f * (pj / kk + prev);
    }

    // Deterministic block reduce.
    for (int o = 16; o > 0; o >>= 1) acc += __shfl_down_sync(0xFFFFFFFFu, acc, o);
    if (lane == 0) wred[wid] = acc;
    __syncthreads();
    if (tid == 0) {
        float u = 0.0f;
#pragma unroll
        for (int w = 0; w < 8; ++w) u += wred[w];
        g_ap[b] = u / (float)GG;

        // Ticket: last block computes the mean. atomicInc wraps 63 -> 0, so the
        // counter self-resets for every graph replay.
        __threadfence();
        unsigned old = atomicInc(&g_ticket, BB - 1);
        if (old == BB - 1) {
            float s = 0.0f;
#pragma unroll
            for (int i = 0; i < BB; ++i) s += g_ap[i];   // fixed order
            out[0] = s * (1.0f / (float)BB);
        }
    }
}

// ---------------------------------------------------------------------------
extern "C" void kernel_launch(void* const* d_in, const int* in_sizes, int n_in,
                              void* d_out, int out_size)
{
    const float* pred_boxes   = (const float*)d_in[0];
    const float* pred_scores  = (const float*)d_in[1];
    const int*   pred_classes = (const int*)d_in[2];
    const float* gt_boxes     = (const float*)d_in[3];
    const int*   gt_classes   = (const int*)d_in[4];
    float* out = (float*)d_out;

    dim3 g1(PP / 512, BB, NZ);
    k_bestiou<<<g1, 256>>>(pred_boxes, gt_boxes);
    dim3 g2(PP / 256, BB);
    k_cand<<<g2, 256>>>(pred_scores, pred_classes, gt_classes);
    k_ap2<<<BB, 256>>>(out);
}